// round 3
// baseline (speedup 1.0000x reference)
#include <cuda_runtime.h>
#include <math.h>

// Problem constants (fixed by the dataset)
#define N_ 50000
#define E_ 800000

// ---------------------------------------------------------------------------
// Static device scratch (no allocation allowed)
// ---------------------------------------------------------------------------
__device__ __align__(16) float g_xl[N_ * 128];
__device__ __align__(16) float g_xr[N_ * 128];
__device__ __align__(16) float g_h [N_ * 128];
__device__ int   g_rowptr[N_ + 1];
__device__ int   g_cnt[N_];
__device__ int   g_col[E_];
__device__ int   g_esrc[E_];
__device__ int   g_edst[E_];
__device__ int   g_is64;

// ---------------------------------------------------------------------------
// Edge-index dtype sniffing + normalization to int32
// If buffer is int64 (little-endian, values < 2^31), every odd 32-bit word is
// zero. Sample 4096 odd words; any nonzero => int32.
// ---------------------------------------------------------------------------
__global__ void k_detect(const int* __restrict__ ei32) {
    __shared__ int nz;
    if (threadIdx.x == 0) nz = 0;
    __syncthreads();
    int local = 0;
    for (int i = threadIdx.x; i < 4096; i += blockDim.x)
        local |= ei32[2 * i + 1];
    if (local) atomicOr(&nz, 1);
    __syncthreads();
    if (threadIdx.x == 0) g_is64 = (nz == 0) ? 1 : 0;
}

__global__ void k_convert(const void* __restrict__ ei) {
    int e = blockIdx.x * blockDim.x + threadIdx.x;
    if (e >= E_) return;
    int s, d;
    if (g_is64) {
        const long long* p = (const long long*)ei;
        s = (int)p[e];
        d = (int)p[E_ + e];
    } else {
        const int* p = (const int*)ei;
        s = p[e];
        d = p[E_ + e];
    }
    // Clamp defensively: out-of-range becomes wrong-but-safe.
    s = min(max(s, 0), N_ - 1);
    d = min(max(d, 0), N_ - 1);
    g_esrc[e] = s;
    g_edst[e] = d;
}

// ---------------------------------------------------------------------------
// CSR build: histogram by dst -> exclusive scan -> scatter src ids
// ---------------------------------------------------------------------------
__global__ void k_zero_cnt() {
    int i = blockIdx.x * blockDim.x + threadIdx.x;
    if (i < N_) g_cnt[i] = 0;
}

__global__ void k_hist() {
    int e = blockIdx.x * blockDim.x + threadIdx.x;
    if (e < E_) atomicAdd(&g_cnt[g_edst[e]], 1);
}

__global__ void k_scan() {
    __shared__ int part[1024];
    int t = threadIdx.x;
    const int CH = (N_ + 1023) / 1024;  // 49
    int base = t * CH;
    int sum = 0;
    for (int i = 0; i < CH; i++) {
        int idx = base + i;
        if (idx < N_) sum += g_cnt[idx];
    }
    part[t] = sum;
    __syncthreads();
    for (int off = 1; off < 1024; off <<= 1) {
        int v = (t >= off) ? part[t - off] : 0;
        __syncthreads();
        part[t] += v;
        __syncthreads();
    }
    int run = (t == 0) ? 0 : part[t - 1];
    for (int i = 0; i < CH; i++) {
        int idx = base + i;
        if (idx < N_) {
            int c = g_cnt[idx];
            g_rowptr[idx] = run;
            run += c;
            g_cnt[idx] = 0;   // reset for scatter cursor
        }
    }
    if (t == 1023) g_rowptr[N_] = run;
}

__global__ void k_scatter() {
    int e = blockIdx.x * blockDim.x + threadIdx.x;
    if (e < E_) {
        int d = g_edst[e];
        int p = atomicAdd(&g_cnt[d], 1);
        int pos = g_rowptr[d] + p;
        if (pos >= 0 && pos < E_) g_col[pos] = g_esrc[e];
    }
}

// ---------------------------------------------------------------------------
// Fused dual GEMM: g_xl = A @ Wl, g_xr = A @ Wr   (A: [N,128], W: [128,HALF])
// 64x64 output tile per block, K=128 in two 64-chunks, 4x4 per thread.
// AFROMH: 0 -> A = external x, 1 -> A = g_h
// ---------------------------------------------------------------------------
template <int HALF, int AFROMH>
__global__ void k_gemm(const float* __restrict__ A_ext,
                       const float* __restrict__ Wl,
                       const float* __restrict__ Wr) {
    __shared__ float As[64][68];  // [k][row], padded
    __shared__ float Bs[64][64];  // [k][col]

    const float* A = AFROMH ? (const float*)g_h : A_ext;

    const int HT = HALF / 64;     // column tiles per matrix
    int row0 = blockIdx.x * 64;
    int by = blockIdx.y;
    const float* W = (by < HT) ? Wl : Wr;
    float* O       = (by < HT) ? g_xl : g_xr;
    int colbase = (by % HT) * 64;
    const int ldw = HALF;

    int tid = threadIdx.x;
    int tc = tid & 15, tr = tid >> 4;

    float acc[4][4];
#pragma unroll
    for (int i = 0; i < 4; i++)
#pragma unroll
        for (int j = 0; j < 4; j++) acc[i][j] = 0.f;

    for (int kc = 0; kc < 2; kc++) {
#pragma unroll
        for (int l = 0; l < 4; l++) {
            int idx = tid + l * 256;     // 0..1023
            int r = idx >> 4;
            int k4 = idx & 15;
            float4 v = make_float4(0.f, 0.f, 0.f, 0.f);
            int grow = row0 + r;
            if (grow < N_)
                v = *(const float4*)&A[grow * 128 + kc * 64 + k4 * 4];
            As[k4 * 4 + 0][r] = v.x;
            As[k4 * 4 + 1][r] = v.y;
            As[k4 * 4 + 2][r] = v.z;
            As[k4 * 4 + 3][r] = v.w;
        }
#pragma unroll
        for (int l = 0; l < 4; l++) {
            int idx = tid + l * 256;
            int k = idx >> 4;
            int c4 = idx & 15;
            float4 v = *(const float4*)&W[(kc * 64 + k) * ldw + colbase + c4 * 4];
            *(float4*)&Bs[k][c4 * 4] = v;
        }
        __syncthreads();
#pragma unroll
        for (int k = 0; k < 64; k++) {
            float4 a = *(const float4*)&As[k][tr * 4];
            float4 b = *(const float4*)&Bs[k][tc * 4];
            acc[0][0] += a.x * b.x; acc[0][1] += a.x * b.y; acc[0][2] += a.x * b.z; acc[0][3] += a.x * b.w;
            acc[1][0] += a.y * b.x; acc[1][1] += a.y * b.y; acc[1][2] += a.y * b.z; acc[1][3] += a.y * b.w;
            acc[2][0] += a.z * b.x; acc[2][1] += a.z * b.y; acc[2][2] += a.z * b.z; acc[2][3] += a.z * b.w;
            acc[3][0] += a.w * b.x; acc[3][1] += a.w * b.y; acc[3][2] += a.w * b.z; acc[3][3] += a.w * b.w;
        }
        __syncthreads();
    }
#pragma unroll
    for (int i = 0; i < 4; i++) {
        int grow = row0 + tr * 4 + i;
        if (grow < N_) {
            float4 v = make_float4(acc[i][0], acc[i][1], acc[i][2], acc[i][3]);
            *(float4*)&O[grow * HALF + colbase + tc * 4] = v;
        }
    }
}

// ---------------------------------------------------------------------------
// Edge aggregation: one warp per dst node, online segment softmax, fused
// bias + ELU epilogue (layers 1/2, 128 channels; lane owns 4 channels)
// ---------------------------------------------------------------------------
__device__ __forceinline__ float leaky(float x) { return x > 0.f ? x : 0.2f * x; }

__global__ void k_agg128(const float* __restrict__ att,
                         const float* __restrict__ bias) {
    int gw = (blockIdx.x * blockDim.x + threadIdx.x) >> 5;
    int lane = threadIdx.x & 31;
    if (gw >= N_) return;
    int off = lane * 4;
    float4 xr4 = *(const float4*)&g_xr[gw * 128 + off];
    float4 a4  = *(const float4*)&att[off];
    float4 xls = *(const float4*)&g_xl[gw * 128 + off];

    // self-loop edge (src == dst)
    float p = leaky(xls.x + xr4.x) * a4.x + leaky(xls.y + xr4.y) * a4.y
            + leaky(xls.z + xr4.z) * a4.z + leaky(xls.w + xr4.w) * a4.w;
    p += __shfl_xor_sync(0xffffffffu, p, 1);
    p += __shfl_xor_sync(0xffffffffu, p, 2);
    p += __shfl_xor_sync(0xffffffffu, p, 4);   // per-head e (8 lanes/head)

    float m = p, s = 1.f;
    float4 acc = xls;

    int beg = g_rowptr[gw], end = g_rowptr[gw + 1];
    for (int j = beg; j < end; j++) {
        int src = g_col[j];
        float4 v = *(const float4*)&g_xl[src * 128 + off];
        float q = leaky(v.x + xr4.x) * a4.x + leaky(v.y + xr4.y) * a4.y
                + leaky(v.z + xr4.z) * a4.z + leaky(v.w + xr4.w) * a4.w;
        q += __shfl_xor_sync(0xffffffffu, q, 1);
        q += __shfl_xor_sync(0xffffffffu, q, 2);
        q += __shfl_xor_sync(0xffffffffu, q, 4);
        float nm = fmaxf(m, q);
        float co = __expf(m - nm);
        float w  = __expf(q - nm);
        s = s * co + w;
        acc.x = acc.x * co + w * v.x;
        acc.y = acc.y * co + w * v.y;
        acc.z = acc.z * co + w * v.z;
        acc.w = acc.w * co + w * v.w;
        m = nm;
    }
    float inv = 1.f / s;
    float4 b4 = *(const float4*)&bias[off];
    float4 o;
    o.x = acc.x * inv + b4.x;
    o.y = acc.y * inv + b4.y;
    o.z = acc.z * inv + b4.z;
    o.w = acc.w * inv + b4.w;
    // ELU
    o.x = o.x > 0.f ? o.x : expm1f(o.x);
    o.y = o.y > 0.f ? o.y : expm1f(o.y);
    o.z = o.z > 0.f ? o.z : expm1f(o.z);
    o.w = o.w > 0.f ? o.w : expm1f(o.w);
    *(float4*)&g_h[gw * 128 + off] = o;
}

// ---------------------------------------------------------------------------
// Layer-3 aggregation (64 channels; lane owns 2), fused bias + log_softmax
// ---------------------------------------------------------------------------
__global__ void k_agg64(const float* __restrict__ att,
                        const float* __restrict__ bias,
                        float* __restrict__ outp) {
    int gw = (blockIdx.x * blockDim.x + threadIdx.x) >> 5;
    int lane = threadIdx.x & 31;
    if (gw >= N_) return;
    int off = lane * 2;
    float2 xr2 = *(const float2*)&g_xr[gw * 64 + off];
    float2 a2  = *(const float2*)&att[off];
    float2 xls = *(const float2*)&g_xl[gw * 64 + off];

    float p = leaky(xls.x + xr2.x) * a2.x + leaky(xls.y + xr2.y) * a2.y;
    p += __shfl_xor_sync(0xffffffffu, p, 1);
    p += __shfl_xor_sync(0xffffffffu, p, 2);
    p += __shfl_xor_sync(0xffffffffu, p, 4);

    float m = p, s = 1.f;
    float2 acc = xls;

    int beg = g_rowptr[gw], end = g_rowptr[gw + 1];
    for (int j = beg; j < end; j++) {
        int src = g_col[j];
        float2 v = *(const float2*)&g_xl[src * 64 + off];
        float q = leaky(v.x + xr2.x) * a2.x + leaky(v.y + xr2.y) * a2.y;
        q += __shfl_xor_sync(0xffffffffu, q, 1);
        q += __shfl_xor_sync(0xffffffffu, q, 2);
        q += __shfl_xor_sync(0xffffffffu, q, 4);
        float nm = fmaxf(m, q);
        float co = __expf(m - nm);
        float w  = __expf(q - nm);
        s = s * co + w;
        acc.x = acc.x * co + w * v.x;
        acc.y = acc.y * co + w * v.y;
        m = nm;
    }
    float inv = 1.f / s;
    float o0 = acc.x * inv + bias[off];
    float o1 = acc.y * inv + bias[off + 1];

    // log_softmax across all 64 channels (whole warp)
    float mx = fmaxf(o0, o1);
#pragma unroll
    for (int d = 16; d >= 1; d >>= 1)
        mx = fmaxf(mx, __shfl_xor_sync(0xffffffffu, mx, d));
    float se = __expf(o0 - mx) + __expf(o1 - mx);
#pragma unroll
    for (int d = 16; d >= 1; d >>= 1)
        se += __shfl_xor_sync(0xffffffffu, se, d);
    float lse = logf(se);
    outp[gw * 64 + off]     = o0 - mx - lse;
    outp[gw * 64 + off + 1] = o1 - mx - lse;
}

// ---------------------------------------------------------------------------
// Host launch — kernel launches ONLY (graph-capture safe)
// ---------------------------------------------------------------------------
extern "C" void kernel_launch(void* const* d_in, const int* in_sizes, int n_in,
                              void* d_out, int out_size) {
    const float* x    = (const float*)d_in[0];
    const void*  ei   = d_in[1];
    const float* Wl1  = (const float*)d_in[2];
    const float* Wr1  = (const float*)d_in[3];
    const float* att1 = (const float*)d_in[4];
    const float* b1   = (const float*)d_in[5];
    const float* Wl2  = (const float*)d_in[6];
    const float* Wr2  = (const float*)d_in[7];
    const float* att2 = (const float*)d_in[8];
    const float* b2   = (const float*)d_in[9];
    const float* Wl3  = (const float*)d_in[10];
    const float* Wr3  = (const float*)d_in[11];
    const float* att3 = (const float*)d_in[12];
    const float* b3   = (const float*)d_in[13];
    float* out = (float*)d_out;

    // Edge-index normalization (dtype-agnostic)
    k_detect<<<1, 256>>>((const int*)ei);
    k_convert<<<(E_ + 255) / 256, 256>>>(ei);

    // CSR build (by dst)
    k_zero_cnt<<<(N_ + 255) / 256, 256>>>();
    k_hist<<<(E_ + 255) / 256, 256>>>();
    k_scan<<<1, 1024>>>();
    k_scatter<<<(E_ + 255) / 256, 256>>>();

    dim3 g12((N_ + 63) / 64, 4);   // 256 output cols (Wl|Wr)
    dim3 g3 ((N_ + 63) / 64, 2);   // 128 output cols (Wl3|Wr3)
    int aggBlocks = (N_ * 32 + 255) / 256;

    // Layer 1
    k_gemm<128, 0><<<g12, 256>>>(x, Wl1, Wr1);
    k_agg128<<<aggBlocks, 256>>>(att1, b1);
    // Layer 2
    k_gemm<128, 1><<<g12, 256>>>(nullptr, Wl2, Wr2);
    k_agg128<<<aggBlocks, 256>>>(att2, b2);
    // Layer 3 + log_softmax
    k_gemm<64, 1><<<g3, 256>>>(nullptr, Wl3, Wr3);
    k_agg64<<<aggBlocks, 256>>>(att3, b3, out);
}

// round 4
// speedup vs baseline: 1.4122x; 1.4122x over previous
#include <cuda_runtime.h>
#include <math.h>
#include <stdint.h>

// Problem constants (fixed by the dataset)
#define N_ 50000
#define E_ 800000

// ---------------------------------------------------------------------------
// Static device scratch (no allocation allowed)
// ---------------------------------------------------------------------------
__device__ __align__(16) float g_xl[N_ * 128];
__device__ __align__(16) float g_xr[N_ * 128];
__device__ __align__(16) float g_h [N_ * 128];
__device__ int   g_rowptr[N_ + 1];
__device__ int   g_cnt[N_];
__device__ int   g_col[E_];
__device__ int   g_esrc[E_];
__device__ int   g_edst[E_];
__device__ int   g_is64;

// ---------------------------------------------------------------------------
// Edge-index dtype sniff + convert-to-int32 + dst histogram (fused)
// ---------------------------------------------------------------------------
__global__ void k_detect(const int* __restrict__ ei32) {
    __shared__ int nz;
    if (threadIdx.x == 0) nz = 0;
    __syncthreads();
    int local = 0;
    for (int i = threadIdx.x; i < 4096; i += blockDim.x)
        local |= ei32[2 * i + 1];
    if (local) atomicOr(&nz, 1);
    __syncthreads();
    if (threadIdx.x == 0) g_is64 = (nz == 0) ? 1 : 0;
}

__global__ void k_zero_cnt() {
    int i = blockIdx.x * blockDim.x + threadIdx.x;
    if (i < N_) g_cnt[i] = 0;
}

__global__ void k_convert_hist(const void* __restrict__ ei) {
    int e = blockIdx.x * blockDim.x + threadIdx.x;
    if (e >= E_) return;
    int s, d;
    if (g_is64) {
        const long long* p = (const long long*)ei;
        s = (int)p[e];
        d = (int)p[E_ + e];
    } else {
        const int* p = (const int*)ei;
        s = p[e];
        d = p[E_ + e];
    }
    s = min(max(s, 0), N_ - 1);
    d = min(max(d, 0), N_ - 1);
    g_esrc[e] = s;
    g_edst[e] = d;
    atomicAdd(&g_cnt[d], 1);
}

__global__ void k_scan() {
    __shared__ int part[1024];
    int t = threadIdx.x;
    const int CH = (N_ + 1023) / 1024;  // 49
    int base = t * CH;
    int sum = 0;
    for (int i = 0; i < CH; i++) {
        int idx = base + i;
        if (idx < N_) sum += g_cnt[idx];
    }
    part[t] = sum;
    __syncthreads();
    for (int off = 1; off < 1024; off <<= 1) {
        int v = (t >= off) ? part[t - off] : 0;
        __syncthreads();
        part[t] += v;
        __syncthreads();
    }
    int run = (t == 0) ? 0 : part[t - 1];
    for (int i = 0; i < CH; i++) {
        int idx = base + i;
        if (idx < N_) {
            int c = g_cnt[idx];
            g_rowptr[idx] = run;
            run += c;
            g_cnt[idx] = 0;   // reset for scatter cursor
        }
    }
    if (t == 1023) g_rowptr[N_] = run;
}

__global__ void k_scatter() {
    int e = blockIdx.x * blockDim.x + threadIdx.x;
    if (e < E_) {
        int d = g_edst[e];
        int p = atomicAdd(&g_cnt[d], 1);
        int pos = g_rowptr[d] + p;
        if (pos >= 0 && pos < E_) g_col[pos] = g_esrc[e];
    }
}

// ---------------------------------------------------------------------------
// Tensor-core (tf32 mma.sync) fused dual GEMM:
//   g_xl = A @ Wl, g_xr = A @ Wr   (A: [N,128], W: [128,HALF])
// Block tile 128x64, 8 warps (4 M x 2 N), warp tile 32x32,
// mma.sync.m16n8k8.tf32, K chunked by 32.
// AFROMH: 0 -> A = external x, 1 -> A = g_h
// ---------------------------------------------------------------------------
__device__ __forceinline__ float to_tf32(float x) {
    float r;
    asm("cvt.rna.tf32.f32 %0, %1;" : "=f"(r) : "f"(x));
    return r;
}

__device__ __forceinline__ void mma_tf32(float c[4], const uint32_t a[4], const uint32_t b[2]) {
    asm volatile(
        "mma.sync.aligned.m16n8k8.row.col.f32.tf32.tf32.f32 "
        "{%0,%1,%2,%3}, {%4,%5,%6,%7}, {%8,%9}, {%0,%1,%2,%3};"
        : "+f"(c[0]), "+f"(c[1]), "+f"(c[2]), "+f"(c[3])
        : "r"(a[0]), "r"(a[1]), "r"(a[2]), "r"(a[3]), "r"(b[0]), "r"(b[1]));
}

template <int HALF, int AFROMH>
__global__ void __launch_bounds__(256) k_gemm_tc(const float* __restrict__ A_ext,
                                                 const float* __restrict__ Wl,
                                                 const float* __restrict__ Wr) {
    // A: [row][k] stride 36 -> frag LDS bank = (4*row + k) % 32, conflict-free
    __shared__ float As[128][36];
    // B: [k][n] stride 72 -> frag LDS bank = (8*k + n) % 32, conflict-free
    __shared__ float Bs[32][72];

    const float* A = AFROMH ? (const float*)g_h : A_ext;

    const int HT = HALF / 64;          // 64-col tiles per weight matrix
    int row0 = blockIdx.x * 128;
    int by = blockIdx.y;
    const float* W = (by < HT) ? Wl : Wr;
    float* O       = (by < HT) ? g_xl : g_xr;
    int colbase = (by % HT) * 64;

    int tid  = threadIdx.x;
    int lane = tid & 31;
    int wid  = tid >> 5;
    int warpM = wid & 3;               // 0..3 -> 32-row slab
    int warpN = wid >> 2;              // 0..1 -> 32-col slab
    int g   = lane >> 2;               // groupID
    int tig = lane & 3;                // thread-in-group
    int mrow = warpM * 32;
    int ncol = warpN * 32;

    float c[2][4][4];
#pragma unroll
    for (int mt = 0; mt < 2; mt++)
#pragma unroll
        for (int nt = 0; nt < 4; nt++)
#pragma unroll
            for (int i = 0; i < 4; i++) c[mt][nt][i] = 0.f;

    for (int kc = 0; kc < 4; kc++) {
        // ---- load A chunk (128 rows x 32 k), coalesced, tf32-rounded ----
#pragma unroll
        for (int l = 0; l < 4; l++) {
            int idx = tid + l * 256;       // 0..1023
            int r  = idx >> 3;             // 0..127
            int kq = idx & 7;              // float4 index along k
            int grow = row0 + r;
            float4 v = make_float4(0.f, 0.f, 0.f, 0.f);
            if (grow < N_)
                v = *(const float4*)&A[grow * 128 + kc * 32 + kq * 4];
            float4 t = make_float4(to_tf32(v.x), to_tf32(v.y), to_tf32(v.z), to_tf32(v.w));
            *(float4*)&As[r][kq * 4] = t;
        }
        // ---- load B chunk (32 k x 64 n), coalesced, tf32-rounded ----
#pragma unroll
        for (int l = 0; l < 2; l++) {
            int idx = tid + l * 256;       // 0..511
            int k  = idx >> 4;             // 0..31
            int nq = idx & 15;             // float4 index along n
            float4 v = *(const float4*)&W[(kc * 32 + k) * HALF + colbase + nq * 4];
            float4 t = make_float4(to_tf32(v.x), to_tf32(v.y), to_tf32(v.z), to_tf32(v.w));
            *(float4*)&Bs[k][nq * 4] = t;
        }
        __syncthreads();

#pragma unroll
        for (int ks = 0; ks < 4; ks++) {
            int k0 = ks * 8;
            uint32_t a[2][4], b[4][2];
#pragma unroll
            for (int mt = 0; mt < 2; mt++) {
                int r = mrow + mt * 16 + g;
                a[mt][0] = __float_as_uint(As[r    ][k0 + tig]);
                a[mt][1] = __float_as_uint(As[r + 8][k0 + tig]);
                a[mt][2] = __float_as_uint(As[r    ][k0 + tig + 4]);
                a[mt][3] = __float_as_uint(As[r + 8][k0 + tig + 4]);
            }
#pragma unroll
            for (int nt = 0; nt < 4; nt++) {
                int n = ncol + nt * 8 + g;
                b[nt][0] = __float_as_uint(Bs[k0 + tig    ][n]);
                b[nt][1] = __float_as_uint(Bs[k0 + tig + 4][n]);
            }
#pragma unroll
            for (int mt = 0; mt < 2; mt++)
#pragma unroll
                for (int nt = 0; nt < 4; nt++)
                    mma_tf32(c[mt][nt], a[mt], b[nt]);
        }
        __syncthreads();
    }

    // ---- epilogue ----
#pragma unroll
    for (int mt = 0; mt < 2; mt++) {
        int r0 = row0 + mrow + mt * 16 + g;
#pragma unroll
        for (int nt = 0; nt < 4; nt++) {
            int cb = colbase + ncol + nt * 8 + tig * 2;
            if (r0 < N_)
                *(float2*)&O[r0 * HALF + cb] = make_float2(c[mt][nt][0], c[mt][nt][1]);
            if (r0 + 8 < N_)
                *(float2*)&O[(r0 + 8) * HALF + cb] = make_float2(c[mt][nt][2], c[mt][nt][3]);
        }
    }
}

// ---------------------------------------------------------------------------
// Edge aggregation: one warp per dst node, online segment softmax, fused
// bias + ELU epilogue (layers 1/2, 128 channels; lane owns 4 channels)
// ---------------------------------------------------------------------------
__device__ __forceinline__ float leaky(float x) { return x > 0.f ? x : 0.2f * x; }

__global__ void k_agg128(const float* __restrict__ att,
                         const float* __restrict__ bias) {
    int gw = (blockIdx.x * blockDim.x + threadIdx.x) >> 5;
    int lane = threadIdx.x & 31;
    if (gw >= N_) return;
    int off = lane * 4;
    float4 xr4 = *(const float4*)&g_xr[gw * 128 + off];
    float4 a4  = *(const float4*)&att[off];
    float4 xls = *(const float4*)&g_xl[gw * 128 + off];

    // self-loop edge (src == dst)
    float p = leaky(xls.x + xr4.x) * a4.x + leaky(xls.y + xr4.y) * a4.y
            + leaky(xls.z + xr4.z) * a4.z + leaky(xls.w + xr4.w) * a4.w;
    p += __shfl_xor_sync(0xffffffffu, p, 1);
    p += __shfl_xor_sync(0xffffffffu, p, 2);
    p += __shfl_xor_sync(0xffffffffu, p, 4);   // per-head e (8 lanes/head)

    float m = p, s = 1.f;
    float4 acc = xls;

    int beg = g_rowptr[gw], end = g_rowptr[gw + 1];
    for (int j = beg; j < end; j++) {
        int src = g_col[j];
        float4 v = *(const float4*)&g_xl[src * 128 + off];
        float q = leaky(v.x + xr4.x) * a4.x + leaky(v.y + xr4.y) * a4.y
                + leaky(v.z + xr4.z) * a4.z + leaky(v.w + xr4.w) * a4.w;
        q += __shfl_xor_sync(0xffffffffu, q, 1);
        q += __shfl_xor_sync(0xffffffffu, q, 2);
        q += __shfl_xor_sync(0xffffffffu, q, 4);
        float nm = fmaxf(m, q);
        float co = __expf(m - nm);
        float w  = __expf(q - nm);
        s = s * co + w;
        acc.x = acc.x * co + w * v.x;
        acc.y = acc.y * co + w * v.y;
        acc.z = acc.z * co + w * v.z;
        acc.w = acc.w * co + w * v.w;
        m = nm;
    }
    float inv = 1.f / s;
    float4 b4 = *(const float4*)&bias[off];
    float4 o;
    o.x = acc.x * inv + b4.x;
    o.y = acc.y * inv + b4.y;
    o.z = acc.z * inv + b4.z;
    o.w = acc.w * inv + b4.w;
    // ELU
    o.x = o.x > 0.f ? o.x : expm1f(o.x);
    o.y = o.y > 0.f ? o.y : expm1f(o.y);
    o.z = o.z > 0.f ? o.z : expm1f(o.z);
    o.w = o.w > 0.f ? o.w : expm1f(o.w);
    *(float4*)&g_h[gw * 128 + off] = o;
}

// ---------------------------------------------------------------------------
// Layer-3 aggregation (64 channels; lane owns 2), fused bias + log_softmax
// ---------------------------------------------------------------------------
__global__ void k_agg64(const float* __restrict__ att,
                        const float* __restrict__ bias,
                        float* __restrict__ outp) {
    int gw = (blockIdx.x * blockDim.x + threadIdx.x) >> 5;
    int lane = threadIdx.x & 31;
    if (gw >= N_) return;
    int off = lane * 2;
    float2 xr2 = *(const float2*)&g_xr[gw * 64 + off];
    float2 a2  = *(const float2*)&att[off];
    float2 xls = *(const float2*)&g_xl[gw * 64 + off];

    float p = leaky(xls.x + xr2.x) * a2.x + leaky(xls.y + xr2.y) * a2.y;
    p += __shfl_xor_sync(0xffffffffu, p, 1);
    p += __shfl_xor_sync(0xffffffffu, p, 2);
    p += __shfl_xor_sync(0xffffffffu, p, 4);

    float m = p, s = 1.f;
    float2 acc = xls;

    int beg = g_rowptr[gw], end = g_rowptr[gw + 1];
    for (int j = beg; j < end; j++) {
        int src = g_col[j];
        float2 v = *(const float2*)&g_xl[src * 64 + off];
        float q = leaky(v.x + xr2.x) * a2.x + leaky(v.y + xr2.y) * a2.y;
        q += __shfl_xor_sync(0xffffffffu, q, 1);
        q += __shfl_xor_sync(0xffffffffu, q, 2);
        q += __shfl_xor_sync(0xffffffffu, q, 4);
        float nm = fmaxf(m, q);
        float co = __expf(m - nm);
        float w  = __expf(q - nm);
        s = s * co + w;
        acc.x = acc.x * co + w * v.x;
        acc.y = acc.y * co + w * v.y;
        m = nm;
    }
    float inv = 1.f / s;
    float o0 = acc.x * inv + bias[off];
    float o1 = acc.y * inv + bias[off + 1];

    // log_softmax across all 64 channels (whole warp)
    float mx = fmaxf(o0, o1);
#pragma unroll
    for (int d = 16; d >= 1; d >>= 1)
        mx = fmaxf(mx, __shfl_xor_sync(0xffffffffu, mx, d));
    float se = __expf(o0 - mx) + __expf(o1 - mx);
#pragma unroll
    for (int d = 16; d >= 1; d >>= 1)
        se += __shfl_xor_sync(0xffffffffu, se, d);
    float lse = logf(se);
    outp[gw * 64 + off]     = o0 - mx - lse;
    outp[gw * 64 + off + 1] = o1 - mx - lse;
}

// ---------------------------------------------------------------------------
// Host launch — kernel launches ONLY (graph-capture safe)
// ---------------------------------------------------------------------------
extern "C" void kernel_launch(void* const* d_in, const int* in_sizes, int n_in,
                              void* d_out, int out_size) {
    const float* x    = (const float*)d_in[0];
    const void*  ei   = d_in[1];
    const float* Wl1  = (const float*)d_in[2];
    const float* Wr1  = (const float*)d_in[3];
    const float* att1 = (const float*)d_in[4];
    const float* b1   = (const float*)d_in[5];
    const float* Wl2  = (const float*)d_in[6];
    const float* Wr2  = (const float*)d_in[7];
    const float* att2 = (const float*)d_in[8];
    const float* b2   = (const float*)d_in[9];
    const float* Wl3  = (const float*)d_in[10];
    const float* Wr3  = (const float*)d_in[11];
    const float* att3 = (const float*)d_in[12];
    const float* b3   = (const float*)d_in[13];
    float* out = (float*)d_out;

    // CSR build (by dst)
    k_detect<<<1, 256>>>((const int*)ei);
    k_zero_cnt<<<(N_ + 255) / 256, 256>>>();
    k_convert_hist<<<(E_ + 255) / 256, 256>>>(ei);
    k_scan<<<1, 1024>>>();
    k_scatter<<<(E_ + 255) / 256, 256>>>();

    dim3 g12((N_ + 127) / 128, 4);   // 256 output cols (Wl|Wr)
    dim3 g3 ((N_ + 127) / 128, 2);   // 128 output cols (Wl3|Wr3)
    int aggBlocks = (N_ * 32 + 255) / 256;

    // Layer 1
    k_gemm_tc<128, 0><<<g12, 256>>>(x, Wl1, Wr1);
    k_agg128<<<aggBlocks, 256>>>(att1, b1);
    // Layer 2
    k_gemm_tc<128, 1><<<g12, 256>>>(nullptr, Wl2, Wr2);
    k_agg128<<<aggBlocks, 256>>>(att2, b2);
    // Layer 3 + log_softmax
    k_gemm_tc<64, 1><<<g3, 256>>>(nullptr, Wl3, Wr3);
    k_agg64<<<aggBlocks, 256>>>(att3, b3, out);
}

// round 5
// speedup vs baseline: 1.6832x; 1.1919x over previous
#include <cuda_runtime.h>
#include <math.h>
#include <stdint.h>

// Problem constants (fixed by the dataset)
#define N_ 50000
#define E_ 800000
#define NB_SCAN ((N_ + 1023) / 1024)   // 49

// ---------------------------------------------------------------------------
// Static device scratch (no allocation allowed)
// ---------------------------------------------------------------------------
__device__ __align__(16) float g_xl[N_ * 128];
__device__ __align__(16) float g_xr[N_ * 128];
__device__ __align__(16) float g_h [N_ * 128];
__device__ int   g_rowptr[N_ + 1];
__device__ int   g_cnt[N_];
__device__ int   g_col[E_];
__device__ int   g_esrc[E_];
__device__ int   g_edst[E_];
__device__ int   g_is64;
__device__ int   g_bsum[64];
__device__ int   g_boff[64];

// ---------------------------------------------------------------------------
// Edge-index dtype sniff + convert-to-int32 + dst histogram (fused)
// ---------------------------------------------------------------------------
__global__ void k_detect(const int* __restrict__ ei32) {
    __shared__ int nz;
    if (threadIdx.x == 0) nz = 0;
    __syncthreads();
    int local = 0;
    for (int i = threadIdx.x; i < 4096; i += blockDim.x)
        local |= ei32[2 * i + 1];
    if (local) atomicOr(&nz, 1);
    __syncthreads();
    if (threadIdx.x == 0) g_is64 = (nz == 0) ? 1 : 0;
}

__global__ void k_zero_cnt() {
    int i = blockIdx.x * blockDim.x + threadIdx.x;
    if (i < N_) g_cnt[i] = 0;
}

__global__ void k_convert_hist(const void* __restrict__ ei) {
    int e = blockIdx.x * blockDim.x + threadIdx.x;
    if (e >= E_) return;
    int s, d;
    if (g_is64) {
        const long long* p = (const long long*)ei;
        s = (int)p[e];
        d = (int)p[E_ + e];
    } else {
        const int* p = (const int*)ei;
        s = p[e];
        d = p[E_ + e];
    }
    s = min(max(s, 0), N_ - 1);
    d = min(max(d, 0), N_ - 1);
    g_esrc[e] = s;
    g_edst[e] = d;
    atomicAdd(&g_cnt[d], 1);
}

// ---------------------------------------------------------------------------
// Multi-block exclusive scan of g_cnt -> g_rowptr (3 phases)
// ---------------------------------------------------------------------------
__global__ void k_scan1() {                 // grid NB_SCAN, block 1024
    __shared__ int sh[1024];
    int b = blockIdx.x, t = threadIdx.x;
    int idx = b * 1024 + t;
    int v = (idx < N_) ? g_cnt[idx] : 0;
    sh[t] = v;
    __syncthreads();
#pragma unroll
    for (int off = 1; off < 1024; off <<= 1) {
        int x = (t >= off) ? sh[t - off] : 0;
        __syncthreads();
        sh[t] += x;
        __syncthreads();
    }
    if (idx < N_) g_rowptr[idx] = sh[t] - v;  // exclusive
    if (t == 1023) g_bsum[b] = sh[1023];
}

__global__ void k_scan2() {                 // 1 block, 64 threads
    __shared__ int sh[64];
    int t = threadIdx.x;
    int v = (t < NB_SCAN) ? g_bsum[t] : 0;
    sh[t] = v;
    __syncthreads();
#pragma unroll
    for (int off = 1; off < 64; off <<= 1) {
        int x = (t >= off) ? sh[t - off] : 0;
        __syncthreads();
        sh[t] += x;
        __syncthreads();
    }
    if (t < NB_SCAN) g_boff[t] = sh[t] - v;   // exclusive block offsets
    if (t == 63) g_rowptr[N_] = sh[63];       // total
}

__global__ void k_scan3() {                 // add offsets + reset cursor
    int i = blockIdx.x * blockDim.x + threadIdx.x;
    if (i < N_) {
        g_rowptr[i] += g_boff[i >> 10];
        g_cnt[i] = 0;
    }
}

__global__ void k_scatter() {
    int e = blockIdx.x * blockDim.x + threadIdx.x;
    if (e < E_) {
        int d = g_edst[e];
        int p = atomicAdd(&g_cnt[d], 1);
        int pos = g_rowptr[d] + p;
        if (pos >= 0 && pos < E_) g_col[pos] = g_esrc[e];
    }
}

// ---------------------------------------------------------------------------
// Tensor-core (tf32 mma.sync) fused dual GEMM:
//   g_xl = A @ Wl, g_xr = A @ Wr   (A: [N,128], W: [128,HALF])
// Block tile 128x64, 8 warps (4 M x 2 N), warp tile 32x32,
// mma.sync.m16n8k8.tf32, K chunked by 32.
// ---------------------------------------------------------------------------
__device__ __forceinline__ float to_tf32(float x) {
    float r;
    asm("cvt.rna.tf32.f32 %0, %1;" : "=f"(r) : "f"(x));
    return r;
}

__device__ __forceinline__ void mma_tf32(float c[4], const uint32_t a[4], const uint32_t b[2]) {
    asm volatile(
        "mma.sync.aligned.m16n8k8.row.col.f32.tf32.tf32.f32 "
        "{%0,%1,%2,%3}, {%4,%5,%6,%7}, {%8,%9}, {%0,%1,%2,%3};"
        : "+f"(c[0]), "+f"(c[1]), "+f"(c[2]), "+f"(c[3])
        : "r"(a[0]), "r"(a[1]), "r"(a[2]), "r"(a[3]), "r"(b[0]), "r"(b[1]));
}

template <int HALF, int AFROMH>
__global__ void __launch_bounds__(256) k_gemm_tc(const float* __restrict__ A_ext,
                                                 const float* __restrict__ Wl,
                                                 const float* __restrict__ Wr) {
    __shared__ float As[128][36];
    __shared__ float Bs[32][72];

    const float* A = AFROMH ? (const float*)g_h : A_ext;

    const int HT = HALF / 64;
    int row0 = blockIdx.x * 128;
    int by = blockIdx.y;
    const float* W = (by < HT) ? Wl : Wr;
    float* O       = (by < HT) ? g_xl : g_xr;
    int colbase = (by % HT) * 64;

    int tid  = threadIdx.x;
    int lane = tid & 31;
    int wid  = tid >> 5;
    int warpM = wid & 3;
    int warpN = wid >> 2;
    int g   = lane >> 2;
    int tig = lane & 3;
    int mrow = warpM * 32;
    int ncol = warpN * 32;

    float c[2][4][4];
#pragma unroll
    for (int mt = 0; mt < 2; mt++)
#pragma unroll
        for (int nt = 0; nt < 4; nt++)
#pragma unroll
            for (int i = 0; i < 4; i++) c[mt][nt][i] = 0.f;

    for (int kc = 0; kc < 4; kc++) {
#pragma unroll
        for (int l = 0; l < 4; l++) {
            int idx = tid + l * 256;
            int r  = idx >> 3;
            int kq = idx & 7;
            int grow = row0 + r;
            float4 v = make_float4(0.f, 0.f, 0.f, 0.f);
            if (grow < N_)
                v = *(const float4*)&A[grow * 128 + kc * 32 + kq * 4];
            float4 t = make_float4(to_tf32(v.x), to_tf32(v.y), to_tf32(v.z), to_tf32(v.w));
            *(float4*)&As[r][kq * 4] = t;
        }
#pragma unroll
        for (int l = 0; l < 2; l++) {
            int idx = tid + l * 256;
            int k  = idx >> 4;
            int nq = idx & 15;
            float4 v = *(const float4*)&W[(kc * 32 + k) * HALF + colbase + nq * 4];
            float4 t = make_float4(to_tf32(v.x), to_tf32(v.y), to_tf32(v.z), to_tf32(v.w));
            *(float4*)&Bs[k][nq * 4] = t;
        }
        __syncthreads();

#pragma unroll
        for (int ks = 0; ks < 4; ks++) {
            int k0 = ks * 8;
            uint32_t a[2][4], b[4][2];
#pragma unroll
            for (int mt = 0; mt < 2; mt++) {
                int r = mrow + mt * 16 + g;
                a[mt][0] = __float_as_uint(As[r    ][k0 + tig]);
                a[mt][1] = __float_as_uint(As[r + 8][k0 + tig]);
                a[mt][2] = __float_as_uint(As[r    ][k0 + tig + 4]);
                a[mt][3] = __float_as_uint(As[r + 8][k0 + tig + 4]);
            }
#pragma unroll
            for (int nt = 0; nt < 4; nt++) {
                int n = ncol + nt * 8 + g;
                b[nt][0] = __float_as_uint(Bs[k0 + tig    ][n]);
                b[nt][1] = __float_as_uint(Bs[k0 + tig + 4][n]);
            }
#pragma unroll
            for (int mt = 0; mt < 2; mt++)
#pragma unroll
                for (int nt = 0; nt < 4; nt++)
                    mma_tf32(c[mt][nt], a[mt], b[nt]);
        }
        __syncthreads();
    }

#pragma unroll
    for (int mt = 0; mt < 2; mt++) {
        int r0 = row0 + mrow + mt * 16 + g;
#pragma unroll
        for (int nt = 0; nt < 4; nt++) {
            int cb = colbase + ncol + nt * 8 + tig * 2;
            if (r0 < N_)
                *(float2*)&O[r0 * HALF + cb] = make_float2(c[mt][nt][0], c[mt][nt][1]);
            if (r0 + 8 < N_)
                *(float2*)&O[(r0 + 8) * HALF + cb] = make_float2(c[mt][nt][2], c[mt][nt][3]);
        }
    }
}

// ---------------------------------------------------------------------------
// Edge aggregation: one warp per dst node, online segment softmax, fused
// bias + ELU epilogue (layers 1/2, 128 channels; lane owns 4 channels)
// ---------------------------------------------------------------------------
__device__ __forceinline__ float leaky(float x) { return x > 0.f ? x : 0.2f * x; }

__global__ void k_agg128(const float* __restrict__ att,
                         const float* __restrict__ bias) {
    int gw = (blockIdx.x * blockDim.x + threadIdx.x) >> 5;
    int lane = threadIdx.x & 31;
    if (gw >= N_) return;
    int off = lane * 4;
    float4 xr4 = *(const float4*)&g_xr[gw * 128 + off];
    float4 a4  = *(const float4*)&att[off];
    float4 xls = *(const float4*)&g_xl[gw * 128 + off];

    float p = leaky(xls.x + xr4.x) * a4.x + leaky(xls.y + xr4.y) * a4.y
            + leaky(xls.z + xr4.z) * a4.z + leaky(xls.w + xr4.w) * a4.w;
    p += __shfl_xor_sync(0xffffffffu, p, 1);
    p += __shfl_xor_sync(0xffffffffu, p, 2);
    p += __shfl_xor_sync(0xffffffffu, p, 4);

    float m = p, s = 1.f;
    float4 acc = xls;

    int beg = g_rowptr[gw], end = g_rowptr[gw + 1];
    for (int j = beg; j < end; j++) {
        int src = g_col[j];
        float4 v = *(const float4*)&g_xl[src * 128 + off];
        float q = leaky(v.x + xr4.x) * a4.x + leaky(v.y + xr4.y) * a4.y
                + leaky(v.z + xr4.z) * a4.z + leaky(v.w + xr4.w) * a4.w;
        q += __shfl_xor_sync(0xffffffffu, q, 1);
        q += __shfl_xor_sync(0xffffffffu, q, 2);
        q += __shfl_xor_sync(0xffffffffu, q, 4);
        float nm = fmaxf(m, q);
        float co = __expf(m - nm);
        float w  = __expf(q - nm);
        s = s * co + w;
        acc.x = acc.x * co + w * v.x;
        acc.y = acc.y * co + w * v.y;
        acc.z = acc.z * co + w * v.z;
        acc.w = acc.w * co + w * v.w;
        m = nm;
    }
    float inv = 1.f / s;
    float4 b4 = *(const float4*)&bias[off];
    float4 o;
    o.x = acc.x * inv + b4.x;
    o.y = acc.y * inv + b4.y;
    o.z = acc.z * inv + b4.z;
    o.w = acc.w * inv + b4.w;
    o.x = o.x > 0.f ? o.x : expm1f(o.x);
    o.y = o.y > 0.f ? o.y : expm1f(o.y);
    o.z = o.z > 0.f ? o.z : expm1f(o.z);
    o.w = o.w > 0.f ? o.w : expm1f(o.w);
    *(float4*)&g_h[gw * 128 + off] = o;
}

// ---------------------------------------------------------------------------
// Layer-3 aggregation (64 channels; lane owns 2), fused bias + log_softmax
// ---------------------------------------------------------------------------
__global__ void k_agg64(const float* __restrict__ att,
                        const float* __restrict__ bias,
                        float* __restrict__ outp) {
    int gw = (blockIdx.x * blockDim.x + threadIdx.x) >> 5;
    int lane = threadIdx.x & 31;
    if (gw >= N_) return;
    int off = lane * 2;
    float2 xr2 = *(const float2*)&g_xr[gw * 64 + off];
    float2 a2  = *(const float2*)&att[off];
    float2 xls = *(const float2*)&g_xl[gw * 64 + off];

    float p = leaky(xls.x + xr2.x) * a2.x + leaky(xls.y + xr2.y) * a2.y;
    p += __shfl_xor_sync(0xffffffffu, p, 1);
    p += __shfl_xor_sync(0xffffffffu, p, 2);
    p += __shfl_xor_sync(0xffffffffu, p, 4);

    float m = p, s = 1.f;
    float2 acc = xls;

    int beg = g_rowptr[gw], end = g_rowptr[gw + 1];
    for (int j = beg; j < end; j++) {
        int src = g_col[j];
        float2 v = *(const float2*)&g_xl[src * 64 + off];
        float q = leaky(v.x + xr2.x) * a2.x + leaky(v.y + xr2.y) * a2.y;
        q += __shfl_xor_sync(0xffffffffu, q, 1);
        q += __shfl_xor_sync(0xffffffffu, q, 2);
        q += __shfl_xor_sync(0xffffffffu, q, 4);
        float nm = fmaxf(m, q);
        float co = __expf(m - nm);
        float w  = __expf(q - nm);
        s = s * co + w;
        acc.x = acc.x * co + w * v.x;
        acc.y = acc.y * co + w * v.y;
        m = nm;
    }
    float inv = 1.f / s;
    float o0 = acc.x * inv + bias[off];
    float o1 = acc.y * inv + bias[off + 1];

    float mx = fmaxf(o0, o1);
#pragma unroll
    for (int d = 16; d >= 1; d >>= 1)
        mx = fmaxf(mx, __shfl_xor_sync(0xffffffffu, mx, d));
    float se = __expf(o0 - mx) + __expf(o1 - mx);
#pragma unroll
    for (int d = 16; d >= 1; d >>= 1)
        se += __shfl_xor_sync(0xffffffffu, se, d);
    float lse = logf(se);
    outp[gw * 64 + off]     = o0 - mx - lse;
    outp[gw * 64 + off + 1] = o1 - mx - lse;
}

// ---------------------------------------------------------------------------
// Host launch — kernel launches ONLY (graph-capture safe)
// ---------------------------------------------------------------------------
extern "C" void kernel_launch(void* const* d_in, const int* in_sizes, int n_in,
                              void* d_out, int out_size) {
    const float* x    = (const float*)d_in[0];
    const void*  ei   = d_in[1];
    const float* Wl1  = (const float*)d_in[2];
    const float* Wr1  = (const float*)d_in[3];
    const float* att1 = (const float*)d_in[4];
    const float* b1   = (const float*)d_in[5];
    const float* Wl2  = (const float*)d_in[6];
    const float* Wr2  = (const float*)d_in[7];
    const float* att2 = (const float*)d_in[8];
    const float* b2   = (const float*)d_in[9];
    const float* Wl3  = (const float*)d_in[10];
    const float* Wr3  = (const float*)d_in[11];
    const float* att3 = (const float*)d_in[12];
    const float* b3   = (const float*)d_in[13];
    float* out = (float*)d_out;

    // CSR build (by dst)
    k_detect<<<1, 256>>>((const int*)ei);
    k_zero_cnt<<<(N_ + 255) / 256, 256>>>();
    k_convert_hist<<<(E_ + 255) / 256, 256>>>(ei);
    k_scan1<<<NB_SCAN, 1024>>>();
    k_scan2<<<1, 64>>>();
    k_scan3<<<(N_ + 255) / 256, 256>>>();
    k_scatter<<<(E_ + 255) / 256, 256>>>();

    dim3 g12((N_ + 127) / 128, 4);
    dim3 g3 ((N_ + 127) / 128, 2);
    int aggBlocks = (N_ * 32 + 255) / 256;

    // Layer 1
    k_gemm_tc<128, 0><<<g12, 256>>>(x, Wl1, Wr1);
    k_agg128<<<aggBlocks, 256>>>(att1, b1);
    // Layer 2
    k_gemm_tc<128, 1><<<g12, 256>>>(nullptr, Wl2, Wr2);
    k_agg128<<<aggBlocks, 256>>>(att2, b2);
    // Layer 3 + log_softmax
    k_gemm_tc<64, 1><<<g3, 256>>>(nullptr, Wl3, Wr3);
    k_agg64<<<aggBlocks, 256>>>(att3, b3, out);
}

// round 6
// speedup vs baseline: 1.9784x; 1.1754x over previous
#include <cuda_runtime.h>
#include <math.h>
#include <stdint.h>

// Problem constants (fixed by the dataset)
#define N_ 50000
#define E_ 800000
#define NB_SCAN ((N_ + 1023) / 1024)   // 49

// ---------------------------------------------------------------------------
// Static device scratch (no allocation allowed)
// ---------------------------------------------------------------------------
__device__ __align__(16) float g_xl[N_ * 128];
__device__ __align__(16) float g_xr[N_ * 128];
__device__ __align__(16) float g_h [N_ * 128];
__device__ int   g_rowptr[N_ + 1];
__device__ int   g_cnt[N_];
__device__ int   g_col[E_];
__device__ int   g_esrc[E_];
__device__ int   g_edst[E_];
__device__ int   g_is64;
__device__ int   g_bsum[64];
__device__ int   g_boff[64];

// ---------------------------------------------------------------------------
// Edge-index dtype sniff + convert-to-int32 + dst histogram (fused)
// ---------------------------------------------------------------------------
__global__ void k_detect(const int* __restrict__ ei32) {
    __shared__ int nz;
    if (threadIdx.x == 0) nz = 0;
    __syncthreads();
    int local = 0;
    for (int i = threadIdx.x; i < 4096; i += blockDim.x)
        local |= ei32[2 * i + 1];
    if (local) atomicOr(&nz, 1);
    __syncthreads();
    if (threadIdx.x == 0) g_is64 = (nz == 0) ? 1 : 0;
}

__global__ void k_zero_cnt() {
    int i = blockIdx.x * blockDim.x + threadIdx.x;
    if (i < N_) g_cnt[i] = 0;
}

__global__ void k_convert_hist(const void* __restrict__ ei) {
    int e = blockIdx.x * blockDim.x + threadIdx.x;
    if (e >= E_) return;
    int s, d;
    if (g_is64) {
        const long long* p = (const long long*)ei;
        s = (int)p[e];
        d = (int)p[E_ + e];
    } else {
        const int* p = (const int*)ei;
        s = p[e];
        d = p[E_ + e];
    }
    s = min(max(s, 0), N_ - 1);
    d = min(max(d, 0), N_ - 1);
    g_esrc[e] = s;
    g_edst[e] = d;
    atomicAdd(&g_cnt[d], 1);
}

// ---------------------------------------------------------------------------
// Multi-block exclusive scan of g_cnt -> g_rowptr (3 phases)
// ---------------------------------------------------------------------------
__global__ void k_scan1() {
    __shared__ int sh[1024];
    int b = blockIdx.x, t = threadIdx.x;
    int idx = b * 1024 + t;
    int v = (idx < N_) ? g_cnt[idx] : 0;
    sh[t] = v;
    __syncthreads();
#pragma unroll
    for (int off = 1; off < 1024; off <<= 1) {
        int x = (t >= off) ? sh[t - off] : 0;
        __syncthreads();
        sh[t] += x;
        __syncthreads();
    }
    if (idx < N_) g_rowptr[idx] = sh[t] - v;
    if (t == 1023) g_bsum[b] = sh[1023];
}

__global__ void k_scan2() {
    __shared__ int sh[64];
    int t = threadIdx.x;
    int v = (t < NB_SCAN) ? g_bsum[t] : 0;
    sh[t] = v;
    __syncthreads();
#pragma unroll
    for (int off = 1; off < 64; off <<= 1) {
        int x = (t >= off) ? sh[t - off] : 0;
        __syncthreads();
        sh[t] += x;
        __syncthreads();
    }
    if (t < NB_SCAN) g_boff[t] = sh[t] - v;
    if (t == 63) g_rowptr[N_] = sh[63];
}

__global__ void k_scan3() {
    int i = blockIdx.x * blockDim.x + threadIdx.x;
    if (i < N_) {
        g_rowptr[i] += g_boff[i >> 10];
        g_cnt[i] = 0;
    }
}

__global__ void k_scatter() {
    int e = blockIdx.x * blockDim.x + threadIdx.x;
    if (e < E_) {
        int d = g_edst[e];
        int p = atomicAdd(&g_cnt[d], 1);
        int pos = g_rowptr[d] + p;
        if (pos >= 0 && pos < E_) g_col[pos] = g_esrc[e];
    }
}

// ---------------------------------------------------------------------------
// Tensor-core (tf32 mma.sync) fused dual GEMM, double-buffered smem.
//   g_xl = A @ Wl, g_xr = A @ Wr   (A: [N,128], W: [128,HALF])
// Block tile 128x64, 8 warps (4 M x 2 N), warp tile 32x32,
// mma.sync.m16n8k8.tf32, K chunked by 32. Raw fp32 bits fed to tf32 mma
// (HW uses upper 19 bits; truncation ~= rna for this accuracy budget).
// ---------------------------------------------------------------------------
__device__ __forceinline__ void mma_tf32(float c[4], const uint32_t a[4], const uint32_t b[2]) {
    asm volatile(
        "mma.sync.aligned.m16n8k8.row.col.f32.tf32.tf32.f32 "
        "{%0,%1,%2,%3}, {%4,%5,%6,%7}, {%8,%9}, {%0,%1,%2,%3};"
        : "+f"(c[0]), "+f"(c[1]), "+f"(c[2]), "+f"(c[3])
        : "r"(a[0]), "r"(a[1]), "r"(a[2]), "r"(a[3]), "r"(b[0]), "r"(b[1]));
}

template <int HALF, int AFROMH>
__global__ void __launch_bounds__(256) k_gemm_tc(const float* __restrict__ A_ext,
                                                 const float* __restrict__ Wl,
                                                 const float* __restrict__ Wr) {
    __shared__ float As[2][128][36];
    __shared__ float Bs[2][32][72];

    const float* A = AFROMH ? (const float*)g_h : A_ext;

    const int HT = HALF / 64;
    int row0 = blockIdx.x * 128;
    int by = blockIdx.y;
    const float* W = (by < HT) ? Wl : Wr;
    float* O       = (by < HT) ? g_xl : g_xr;
    int colbase = (by % HT) * 64;

    int tid  = threadIdx.x;
    int lane = tid & 31;
    int wid  = tid >> 5;
    int warpM = wid & 3;
    int warpN = wid >> 2;
    int g   = lane >> 2;
    int tig = lane & 3;
    int mrow = warpM * 32;
    int ncol = warpN * 32;

    // Per-thread staging coordinates
    int ra_r[4], ra_kq[4];
    int rb_k[2], rb_nq[2];
#pragma unroll
    for (int l = 0; l < 4; l++) {
        int idx = tid + l * 256;
        ra_r[l]  = idx >> 3;
        ra_kq[l] = idx & 7;
    }
#pragma unroll
    for (int l = 0; l < 2; l++) {
        int idx = tid + l * 256;
        rb_k[l]  = idx >> 4;
        rb_nq[l] = idx & 15;
    }

    float c[2][4][4];
#pragma unroll
    for (int mt = 0; mt < 2; mt++)
#pragma unroll
        for (int nt = 0; nt < 4; nt++)
#pragma unroll
            for (int i = 0; i < 4; i++) c[mt][nt][i] = 0.f;

    // Prologue: load chunk 0 into buffer 0
    {
#pragma unroll
        for (int l = 0; l < 4; l++) {
            int grow = row0 + ra_r[l];
            float4 v = make_float4(0.f, 0.f, 0.f, 0.f);
            if (grow < N_) v = *(const float4*)&A[grow * 128 + ra_kq[l] * 4];
            *(float4*)&As[0][ra_r[l]][ra_kq[l] * 4] = v;
        }
#pragma unroll
        for (int l = 0; l < 2; l++) {
            float4 v = *(const float4*)&W[rb_k[l] * HALF + colbase + rb_nq[l] * 4];
            *(float4*)&Bs[0][rb_k[l]][rb_nq[l] * 4] = v;
        }
    }
    __syncthreads();

    for (int kc = 0; kc < 4; kc++) {
        int cur = kc & 1;
        // Issue next chunk's global loads early (overlap with MMA)
        float4 pa[4], pb[2];
        if (kc < 3) {
            int kn = kc + 1;
#pragma unroll
            for (int l = 0; l < 4; l++) {
                int grow = row0 + ra_r[l];
                pa[l] = make_float4(0.f, 0.f, 0.f, 0.f);
                if (grow < N_) pa[l] = *(const float4*)&A[grow * 128 + kn * 32 + ra_kq[l] * 4];
            }
#pragma unroll
            for (int l = 0; l < 2; l++)
                pb[l] = *(const float4*)&W[(kn * 32 + rb_k[l]) * HALF + colbase + rb_nq[l] * 4];
        }

#pragma unroll
        for (int ks = 0; ks < 4; ks++) {
            int k0 = ks * 8;
            uint32_t a[2][4], b[4][2];
#pragma unroll
            for (int mt = 0; mt < 2; mt++) {
                int r = mrow + mt * 16 + g;
                a[mt][0] = __float_as_uint(As[cur][r    ][k0 + tig]);
                a[mt][1] = __float_as_uint(As[cur][r + 8][k0 + tig]);
                a[mt][2] = __float_as_uint(As[cur][r    ][k0 + tig + 4]);
                a[mt][3] = __float_as_uint(As[cur][r + 8][k0 + tig + 4]);
            }
#pragma unroll
            for (int nt = 0; nt < 4; nt++) {
                int n = ncol + nt * 8 + g;
                b[nt][0] = __float_as_uint(Bs[cur][k0 + tig    ][n]);
                b[nt][1] = __float_as_uint(Bs[cur][k0 + tig + 4][n]);
            }
#pragma unroll
            for (int mt = 0; mt < 2; mt++)
#pragma unroll
                for (int nt = 0; nt < 4; nt++)
                    mma_tf32(c[mt][nt], a[mt], b[nt]);
        }

        if (kc < 3) {
            int nxt = cur ^ 1;
#pragma unroll
            for (int l = 0; l < 4; l++)
                *(float4*)&As[nxt][ra_r[l]][ra_kq[l] * 4] = pa[l];
#pragma unroll
            for (int l = 0; l < 2; l++)
                *(float4*)&Bs[nxt][rb_k[l]][rb_nq[l] * 4] = pb[l];
        }
        __syncthreads();
    }

#pragma unroll
    for (int mt = 0; mt < 2; mt++) {
        int r0 = row0 + mrow + mt * 16 + g;
#pragma unroll
        for (int nt = 0; nt < 4; nt++) {
            int cb = colbase + ncol + nt * 8 + tig * 2;
            if (r0 < N_)
                *(float2*)&O[r0 * HALF + cb] = make_float2(c[mt][nt][0], c[mt][nt][1]);
            if (r0 + 8 < N_)
                *(float2*)&O[(r0 + 8) * HALF + cb] = make_float2(c[mt][nt][2], c[mt][nt][3]);
        }
    }
}

// ---------------------------------------------------------------------------
// Edge aggregation: one warp per dst node, online segment softmax, 2-edge
// unrolled (two gathers in flight), fused bias + ELU (layers 1/2)
// ---------------------------------------------------------------------------
__device__ __forceinline__ float leaky(float x) { return x > 0.f ? x : 0.2f * x; }

__global__ void k_agg128(const float* __restrict__ att,
                         const float* __restrict__ bias) {
    int gw = (blockIdx.x * blockDim.x + threadIdx.x) >> 5;
    int lane = threadIdx.x & 31;
    if (gw >= N_) return;
    int off = lane * 4;
    float4 xr4 = *(const float4*)&g_xr[gw * 128 + off];
    float4 a4  = *(const float4*)&att[off];
    float4 xls = *(const float4*)&g_xl[gw * 128 + off];

    // self-loop
    float p = leaky(xls.x + xr4.x) * a4.x + leaky(xls.y + xr4.y) * a4.y
            + leaky(xls.z + xr4.z) * a4.z + leaky(xls.w + xr4.w) * a4.w;
    p += __shfl_xor_sync(0xffffffffu, p, 1);
    p += __shfl_xor_sync(0xffffffffu, p, 2);
    p += __shfl_xor_sync(0xffffffffu, p, 4);

    float m = p, s = 1.f;
    float4 acc = xls;

    int beg = g_rowptr[gw], end = g_rowptr[gw + 1];
    int j = beg;
    for (; j + 1 < end; j += 2) {
        int s0 = g_col[j];
        int s1 = g_col[j + 1];
        float4 v0 = *(const float4*)&g_xl[s0 * 128 + off];
        float4 v1 = *(const float4*)&g_xl[s1 * 128 + off];
        float q0 = leaky(v0.x + xr4.x) * a4.x + leaky(v0.y + xr4.y) * a4.y
                 + leaky(v0.z + xr4.z) * a4.z + leaky(v0.w + xr4.w) * a4.w;
        float q1 = leaky(v1.x + xr4.x) * a4.x + leaky(v1.y + xr4.y) * a4.y
                 + leaky(v1.z + xr4.z) * a4.z + leaky(v1.w + xr4.w) * a4.w;
        q0 += __shfl_xor_sync(0xffffffffu, q0, 1);
        q1 += __shfl_xor_sync(0xffffffffu, q1, 1);
        q0 += __shfl_xor_sync(0xffffffffu, q0, 2);
        q1 += __shfl_xor_sync(0xffffffffu, q1, 2);
        q0 += __shfl_xor_sync(0xffffffffu, q0, 4);
        q1 += __shfl_xor_sync(0xffffffffu, q1, 4);
        float nm = fmaxf(m, fmaxf(q0, q1));
        float co = __expf(m - nm);
        float w0 = __expf(q0 - nm);
        float w1 = __expf(q1 - nm);
        s = s * co + w0 + w1;
        acc.x = acc.x * co + w0 * v0.x + w1 * v1.x;
        acc.y = acc.y * co + w0 * v0.y + w1 * v1.y;
        acc.z = acc.z * co + w0 * v0.z + w1 * v1.z;
        acc.w = acc.w * co + w0 * v0.w + w1 * v1.w;
        m = nm;
    }
    if (j < end) {
        int src = g_col[j];
        float4 v = *(const float4*)&g_xl[src * 128 + off];
        float q = leaky(v.x + xr4.x) * a4.x + leaky(v.y + xr4.y) * a4.y
                + leaky(v.z + xr4.z) * a4.z + leaky(v.w + xr4.w) * a4.w;
        q += __shfl_xor_sync(0xffffffffu, q, 1);
        q += __shfl_xor_sync(0xffffffffu, q, 2);
        q += __shfl_xor_sync(0xffffffffu, q, 4);
        float nm = fmaxf(m, q);
        float co = __expf(m - nm);
        float w  = __expf(q - nm);
        s = s * co + w;
        acc.x = acc.x * co + w * v.x;
        acc.y = acc.y * co + w * v.y;
        acc.z = acc.z * co + w * v.z;
        acc.w = acc.w * co + w * v.w;
        m = nm;
    }
    float inv = 1.f / s;
    float4 b4 = *(const float4*)&bias[off];
    float4 o;
    o.x = acc.x * inv + b4.x;
    o.y = acc.y * inv + b4.y;
    o.z = acc.z * inv + b4.z;
    o.w = acc.w * inv + b4.w;
    o.x = o.x > 0.f ? o.x : expm1f(o.x);
    o.y = o.y > 0.f ? o.y : expm1f(o.y);
    o.z = o.z > 0.f ? o.z : expm1f(o.z);
    o.w = o.w > 0.f ? o.w : expm1f(o.w);
    *(float4*)&g_h[gw * 128 + off] = o;
}

// ---------------------------------------------------------------------------
// Layer-3 aggregation (64 channels; lane owns 2), fused bias + log_softmax
// ---------------------------------------------------------------------------
__global__ void k_agg64(const float* __restrict__ att,
                        const float* __restrict__ bias,
                        float* __restrict__ outp) {
    int gw = (blockIdx.x * blockDim.x + threadIdx.x) >> 5;
    int lane = threadIdx.x & 31;
    if (gw >= N_) return;
    int off = lane * 2;
    float2 xr2 = *(const float2*)&g_xr[gw * 64 + off];
    float2 a2  = *(const float2*)&att[off];
    float2 xls = *(const float2*)&g_xl[gw * 64 + off];

    float p = leaky(xls.x + xr2.x) * a2.x + leaky(xls.y + xr2.y) * a2.y;
    p += __shfl_xor_sync(0xffffffffu, p, 1);
    p += __shfl_xor_sync(0xffffffffu, p, 2);
    p += __shfl_xor_sync(0xffffffffu, p, 4);

    float m = p, s = 1.f;
    float2 acc = xls;

    int beg = g_rowptr[gw], end = g_rowptr[gw + 1];
    int j = beg;
    for (; j + 1 < end; j += 2) {
        int s0 = g_col[j];
        int s1 = g_col[j + 1];
        float2 v0 = *(const float2*)&g_xl[s0 * 64 + off];
        float2 v1 = *(const float2*)&g_xl[s1 * 64 + off];
        float q0 = leaky(v0.x + xr2.x) * a2.x + leaky(v0.y + xr2.y) * a2.y;
        float q1 = leaky(v1.x + xr2.x) * a2.x + leaky(v1.y + xr2.y) * a2.y;
        q0 += __shfl_xor_sync(0xffffffffu, q0, 1);
        q1 += __shfl_xor_sync(0xffffffffu, q1, 1);
        q0 += __shfl_xor_sync(0xffffffffu, q0, 2);
        q1 += __shfl_xor_sync(0xffffffffu, q1, 2);
        q0 += __shfl_xor_sync(0xffffffffu, q0, 4);
        q1 += __shfl_xor_sync(0xffffffffu, q1, 4);
        float nm = fmaxf(m, fmaxf(q0, q1));
        float co = __expf(m - nm);
        float w0 = __expf(q0 - nm);
        float w1 = __expf(q1 - nm);
        s = s * co + w0 + w1;
        acc.x = acc.x * co + w0 * v0.x + w1 * v1.x;
        acc.y = acc.y * co + w0 * v0.y + w1 * v1.y;
        m = nm;
    }
    if (j < end) {
        int src = g_col[j];
        float2 v = *(const float2*)&g_xl[src * 64 + off];
        float q = leaky(v.x + xr2.x) * a2.x + leaky(v.y + xr2.y) * a2.y;
        q += __shfl_xor_sync(0xffffffffu, q, 1);
        q += __shfl_xor_sync(0xffffffffu, q, 2);
        q += __shfl_xor_sync(0xffffffffu, q, 4);
        float nm = fmaxf(m, q);
        float co = __expf(m - nm);
        float w  = __expf(q - nm);
        s = s * co + w;
        acc.x = acc.x * co + w * v.x;
        acc.y = acc.y * co + w * v.y;
        m = nm;
    }
    float inv = 1.f / s;
    float o0 = acc.x * inv + bias[off];
    float o1 = acc.y * inv + bias[off + 1];

    float mx = fmaxf(o0, o1);
#pragma unroll
    for (int d = 16; d >= 1; d >>= 1)
        mx = fmaxf(mx, __shfl_xor_sync(0xffffffffu, mx, d));
    float se = __expf(o0 - mx) + __expf(o1 - mx);
#pragma unroll
    for (int d = 16; d >= 1; d >>= 1)
        se += __shfl_xor_sync(0xffffffffu, se, d);
    float lse = logf(se);
    outp[gw * 64 + off]     = o0 - mx - lse;
    outp[gw * 64 + off + 1] = o1 - mx - lse;
}

// ---------------------------------------------------------------------------
// Host launch — graph-capture-safe fork/join: CSR build runs on a side
// stream concurrently with the layer-1 GEMM; joined before aggregation.
// ---------------------------------------------------------------------------
extern "C" void kernel_launch(void* const* d_in, const int* in_sizes, int n_in,
                              void* d_out, int out_size) {
    const float* x    = (const float*)d_in[0];
    const void*  ei   = d_in[1];
    const float* Wl1  = (const float*)d_in[2];
    const float* Wr1  = (const float*)d_in[3];
    const float* att1 = (const float*)d_in[4];
    const float* b1   = (const float*)d_in[5];
    const float* Wl2  = (const float*)d_in[6];
    const float* Wr2  = (const float*)d_in[7];
    const float* att2 = (const float*)d_in[8];
    const float* b2   = (const float*)d_in[9];
    const float* Wl3  = (const float*)d_in[10];
    const float* Wr3  = (const float*)d_in[11];
    const float* att3 = (const float*)d_in[12];
    const float* b3   = (const float*)d_in[13];
    float* out = (float*)d_out;

    // One-time handle creation (no device memory involved; work enqueued per
    // call is identical every time).
    static cudaStream_t s2 = nullptr;
    static cudaEvent_t evFork = nullptr, evJoin = nullptr;
    if (s2 == nullptr) {
        cudaStreamCreateWithFlags(&s2, cudaStreamNonBlocking);
        cudaEventCreateWithFlags(&evFork, cudaEventDisableTiming);
        cudaEventCreateWithFlags(&evJoin, cudaEventDisableTiming);
    }

    dim3 g12((N_ + 127) / 128, 4);
    dim3 g3 ((N_ + 127) / 128, 2);
    int aggBlocks = (N_ * 32 + 255) / 256;

    // Fork: CSR build on s2, concurrent with layer-1 GEMM on main stream
    cudaEventRecord(evFork, 0);
    cudaStreamWaitEvent(s2, evFork, 0);

    k_detect<<<1, 256, 0, s2>>>((const int*)ei);
    k_zero_cnt<<<(N_ + 255) / 256, 256, 0, s2>>>();
    k_convert_hist<<<(E_ + 255) / 256, 256, 0, s2>>>(ei);
    k_scan1<<<NB_SCAN, 1024, 0, s2>>>();
    k_scan2<<<1, 64, 0, s2>>>();
    k_scan3<<<(N_ + 255) / 256, 256, 0, s2>>>();
    k_scatter<<<(E_ + 255) / 256, 256, 0, s2>>>();
    cudaEventRecord(evJoin, s2);

    // Layer-1 GEMM on main stream (independent of CSR)
    k_gemm_tc<128, 0><<<g12, 256>>>(x, Wl1, Wr1);

    // Join: aggregation needs both GEMM-1 and CSR
    cudaStreamWaitEvent(0, evJoin, 0);

    k_agg128<<<aggBlocks, 256>>>(att1, b1);
    // Layer 2
    k_gemm_tc<128, 1><<<g12, 256>>>(nullptr, Wl2, Wr2);
    k_agg128<<<aggBlocks, 256>>>(att2, b2);
    // Layer 3 + log_softmax
    k_gemm_tc<64, 1><<<g3, 256>>>(nullptr, Wl3, Wr3);
    k_agg64<<<aggBlocks, 256>>>(att3, b3, out);
}